// round 2
// baseline (speedup 1.0000x reference)
#include <cuda_runtime.h>

#define NN   100000
#define DD   128
#define EE   600000
#define SS   2
#define HIDN 80
#define NOUT 2

// Scratch (allocation-free: __device__ globals)
__device__ __align__(16) unsigned char g_mask[SS * NN];  // dst-indicator per edge set
__device__ float g_sum[SS * DD];                         // masked column sums

// ---------------------------------------------------------------------------
// K1: zero masks + accumulators
// ---------------------------------------------------------------------------
__global__ void k_zero() {
    int idx = blockIdx.x * blockDim.x + threadIdx.x;
    int stride = gridDim.x * blockDim.x;
    uint4* m = reinterpret_cast<uint4*>(g_mask);
    const int total16 = (SS * NN) / 16;  // 12500
    for (int i = idx; i < total16; i += stride)
        m[i] = make_uint4(0u, 0u, 0u, 0u);
    if (idx < SS * DD) g_sum[idx] = 0.0f;
}

// ---------------------------------------------------------------------------
// K2: mark nodes that appear as dst in each edge set
// edges layout: (S, E, 2) int32 -> int2 per edge, .y = dst
// ---------------------------------------------------------------------------
__global__ void k_mask(const int2* __restrict__ edges) {
    int e = blockIdx.x * blockDim.x + threadIdx.x;
    const int total = SS * EE;
    if (e >= total) return;
    int2 v = edges[e];
    int s_off = (e >= EE) ? NN : 0;
    g_mask[s_off + v.y] = 1;
}

// ---------------------------------------------------------------------------
// K3: masked column sums of nodes (N x D). Thread = column. Block grid-strides
// over rows, unrolled x4 for MLP.
// ---------------------------------------------------------------------------
__global__ void k_sum(const float* __restrict__ nodes) {
    const int d = threadIdx.x;  // 0..127
    const int G = gridDim.x;
    float a0 = 0.0f, a1 = 0.0f;

    for (int n0 = blockIdx.x; n0 < NN; n0 += 4 * G) {
#pragma unroll
        for (int u = 0; u < 4; u++) {
            int n = n0 + u * G;
            if (n < NN) {
                float v = nodes[(size_t)n * DD + d];
                unsigned char m0 = g_mask[n];
                unsigned char m1 = g_mask[NN + n];
                a0 += m0 ? v : 0.0f;
                a1 += m1 ? v : 0.0f;
            }
        }
    }
    atomicAdd(&g_sum[d], a0);
    atomicAdd(&g_sum[DD + d], a1);
}

// ---------------------------------------------------------------------------
// K4: epilogue — t = sum0@W0 + sum1@W1, g = t/N, then MLP 129->80->80->2
// One block, 128 threads.
// ---------------------------------------------------------------------------
__device__ __forceinline__ float lrelu(float x) {
    return x > 0.0f ? x : 0.01f * x;
}

__global__ void k_final(const float* __restrict__ W,
                        const float* __restrict__ pt,
                        const float* __restrict__ fc1w, const float* __restrict__ fc1b,
                        const float* __restrict__ fc2w, const float* __restrict__ fc2b,
                        const float* __restrict__ fc3w, const float* __restrict__ fc3b,
                        float* __restrict__ out) {
    __shared__ float s0[DD], s1[DD], x[DD + 1], h1[HIDN], h2[HIDN];
    const int t = threadIdx.x;  // 128 threads

    s0[t] = g_sum[t];
    s1[t] = g_sum[DD + t];
    __syncthreads();

    // t_d = sum_k s0[k]*W[0][k][d] + s1[k]*W[1][k][d]   (coalesced over d)
    float acc = 0.0f;
#pragma unroll 8
    for (int k = 0; k < DD; k++) {
        acc += s0[k] * W[k * DD + t];
        acc += s1[k] * W[DD * DD + k * DD + t];
    }
    x[t] = acc / (float)NN;
    if (t == 0) x[DD] = pt[0];
    __syncthreads();

    if (t < HIDN) {
        float a = fc1b[t];
#pragma unroll 8
        for (int j = 0; j < DD + 1; j++) a += x[j] * fc1w[t * (DD + 1) + j];
        h1[t] = lrelu(a);
    }
    __syncthreads();

    if (t < HIDN) {
        float a = fc2b[t];
#pragma unroll 8
        for (int j = 0; j < HIDN; j++) a += h1[j] * fc2w[t * HIDN + j];
        h2[t] = lrelu(a);
    }
    __syncthreads();

    if (t < NOUT) {
        float a = fc3b[t];
#pragma unroll 8
        for (int j = 0; j < HIDN; j++) a += h2[j] * fc3w[t * HIDN + j];
        out[t] = a;
    }
}

// ---------------------------------------------------------------------------
// Input order (metadata): nodes, edges, problem_type, W, att_w, att_b,
//                         fc1_w, fc1_b, fc2_w, fc2_b, fc3_w, fc3_b
// ---------------------------------------------------------------------------
extern "C" void kernel_launch(void* const* d_in, const int* in_sizes, int n_in,
                              void* d_out, int out_size) {
    const float* nodes = (const float*)d_in[0];
    const int2*  edges = (const int2*)d_in[1];
    const float* pt    = (const float*)d_in[2];
    const float* W     = (const float*)d_in[3];
    // d_in[4] att_w, d_in[5] att_b: provably unused (softmax sums to 1)
    const float* fc1w  = (const float*)d_in[6];
    const float* fc1b  = (const float*)d_in[7];
    const float* fc2w  = (const float*)d_in[8];
    const float* fc2b  = (const float*)d_in[9];
    const float* fc3w  = (const float*)d_in[10];
    const float* fc3b  = (const float*)d_in[11];
    float* out = (float*)d_out;

    k_zero<<<64, 256>>>();
    k_mask<<<(SS * EE + 255) / 256, 256>>>(edges);
    k_sum<<<592, DD>>>(nodes);
    k_final<<<1, DD>>>(W, pt, fc1w, fc1b, fc2w, fc2b, fc3w, fc3b, out);
}

// round 3
// speedup vs baseline: 1.1435x; 1.1435x over previous
#include <cuda_runtime.h>

#define NN   100000
#define DD   128
#define EE   600000
#define SS   2
#define HIDN 80
#define NOUT 2

// Scratch (allocation-free: __device__ globals)
__device__ __align__(16) unsigned char g_mask[SS * NN];  // dst-indicator per edge set
__device__ float g_sum[SS * DD];                         // masked column sums
__device__ float g_x[DD];                                // gemv result (pre /N)

// ---------------------------------------------------------------------------
// K1: zero masks + accumulators
// ---------------------------------------------------------------------------
__global__ void k_zero() {
    int idx = blockIdx.x * blockDim.x + threadIdx.x;
    int stride = gridDim.x * blockDim.x;
    uint4* m = reinterpret_cast<uint4*>(g_mask);
    const int total16 = (SS * NN) / 16;  // 12500
    for (int i = idx; i < total16; i += stride)
        m[i] = make_uint4(0u, 0u, 0u, 0u);
    if (idx < SS * DD) g_sum[idx] = 0.0f;
    if (idx < DD) g_x[idx] = 0.0f;
}

// ---------------------------------------------------------------------------
// K2: mark nodes that appear as dst in each edge set
// edges layout: (S, E, 2) int32 -> int2 per edge, .y = dst
// ---------------------------------------------------------------------------
__global__ void k_mask(const int2* __restrict__ edges) {
    int e = blockIdx.x * blockDim.x + threadIdx.x;
    const int total = SS * EE;
    if (e >= total) return;
    int2 v = edges[e];
    int s_off = (e >= EE) ? NN : 0;
    g_mask[s_off + v.y] = 1;
}

// ---------------------------------------------------------------------------
// K3: masked column sums of nodes (N x D). Thread = column. Block grid-strides
// over rows, unrolled x4 for MLP. HBM-bound: 51.2 MB stream.
// ---------------------------------------------------------------------------
__global__ void k_sum(const float* __restrict__ nodes) {
    const int d = threadIdx.x;  // 0..127
    const int G = gridDim.x;
    float a0 = 0.0f, a1 = 0.0f;

    for (int n0 = blockIdx.x; n0 < NN; n0 += 4 * G) {
#pragma unroll
        for (int u = 0; u < 4; u++) {
            int n = n0 + u * G;
            if (n < NN) {
                float v = nodes[(size_t)n * DD + d];
                float m0 = (float)g_mask[n];
                float m1 = (float)g_mask[NN + n];
                a0 += v * m0;
                a1 += v * m1;
            }
        }
    }
    atomicAdd(&g_sum[d], a0);
    atomicAdd(&g_sum[DD + d], a1);
}

// ---------------------------------------------------------------------------
// K4: wide GEMV  x_d = sum_k s0[k]*W0[k][d] + s1[k]*W1[k][d]
// 32 blocks x 128 threads; block b handles k in [8b, 8b+8) for BOTH sets.
// Coalesced W loads spread across 32 SMs -> DRAM latency hidden.
// ---------------------------------------------------------------------------
#define GEMV_BLOCKS 32
#define ROWS_PER_BLK (DD / GEMV_BLOCKS)   // 4... careful: 128/32 = 4

__global__ void k_gemv(const float* __restrict__ W) {
    const int t = threadIdx.x;            // output column d
    const int b = blockIdx.x;             // 0..31
    float acc = 0.0f;
#pragma unroll
    for (int r = 0; r < ROWS_PER_BLK; r++) {
        int k = b * ROWS_PER_BLK + r;
        float s0 = g_sum[k];
        float s1 = g_sum[DD + k];
        acc += s0 * W[k * DD + t];
        acc += s1 * W[DD * DD + k * DD + t];
    }
    atomicAdd(&g_x[t], acc);
}

// ---------------------------------------------------------------------------
// K5: MLP 129 -> 80 -> 80 -> 2, one block of 1024 threads, warp-per-row.
// ---------------------------------------------------------------------------
__device__ __forceinline__ float lrelu(float x) {
    return x > 0.0f ? x : 0.01f * x;
}

__device__ __forceinline__ float warp_reduce(float v) {
#pragma unroll
    for (int off = 16; off > 0; off >>= 1)
        v += __shfl_down_sync(0xFFFFFFFFu, v, off);
    return v;
}

__global__ void k_mlp(const float* __restrict__ pt,
                      const float* __restrict__ fc1w, const float* __restrict__ fc1b,
                      const float* __restrict__ fc2w, const float* __restrict__ fc2b,
                      const float* __restrict__ fc3w, const float* __restrict__ fc3b,
                      float* __restrict__ out) {
    __shared__ float x[DD + 1], h1[HIDN], h2[HIDN];
    const int t    = threadIdx.x;     // 0..1023
    const int warp = t >> 5;          // 0..31
    const int lane = t & 31;

    if (t < DD) x[t] = g_x[t] * (1.0f / (float)NN);
    if (t == DD) x[DD] = pt[0];
    __syncthreads();

    // fc1: 80 rows x 129 cols, warp-per-row (rows warp, warp+32, warp+64)
    for (int row = warp; row < HIDN; row += 32) {
        float a = 0.0f;
        for (int j = lane; j < DD + 1; j += 32)
            a += x[j] * fc1w[row * (DD + 1) + j];
        a = warp_reduce(a);
        if (lane == 0) h1[row] = lrelu(a + fc1b[row]);
    }
    __syncthreads();

    // fc2: 80 rows x 80 cols
    for (int row = warp; row < HIDN; row += 32) {
        float a = 0.0f;
        for (int j = lane; j < HIDN; j += 32)
            a += h1[j] * fc2w[row * HIDN + j];
        a = warp_reduce(a);
        if (lane == 0) h2[row] = lrelu(a + fc2b[row]);
    }
    __syncthreads();

    // fc3: 2 rows x 80 cols
    if (warp < NOUT) {
        float a = 0.0f;
        for (int j = lane; j < HIDN; j += 32)
            a += h2[j] * fc3w[warp * HIDN + j];
        a = warp_reduce(a);
        if (lane == 0) out[warp] = a + fc3b[warp];
    }
}

// ---------------------------------------------------------------------------
// Input order (metadata): nodes, edges, problem_type, W, att_w, att_b,
//                         fc1_w, fc1_b, fc2_w, fc2_b, fc3_w, fc3_b
// ---------------------------------------------------------------------------
extern "C" void kernel_launch(void* const* d_in, const int* in_sizes, int n_in,
                              void* d_out, int out_size) {
    const float* nodes = (const float*)d_in[0];
    const int2*  edges = (const int2*)d_in[1];
    const float* pt    = (const float*)d_in[2];
    const float* W     = (const float*)d_in[3];
    // d_in[4] att_w, d_in[5] att_b: provably unused (softmax sums to 1)
    const float* fc1w  = (const float*)d_in[6];
    const float* fc1b  = (const float*)d_in[7];
    const float* fc2w  = (const float*)d_in[8];
    const float* fc2b  = (const float*)d_in[9];
    const float* fc3w  = (const float*)d_in[10];
    const float* fc3b  = (const float*)d_in[11];
    float* out = (float*)d_out;

    k_zero<<<64, 256>>>();
    k_mask<<<(SS * EE + 255) / 256, 256>>>(edges);
    k_sum<<<592, DD>>>(nodes);
    k_gemv<<<GEMV_BLOCKS, DD>>>(W);
    k_mlp<<<1, 1024>>>(pt, fc1w, fc1b, fc2w, fc2b, fc3w, fc3b, out);
}